// round 12
// baseline (speedup 1.0000x reference)
#include <cuda_runtime.h>
#include <cuda_bf16.h>
#include <math.h>
#include <stdint.h>

// ---------------------------------------------------------------- constants
constexpr int Bn   = 16;
constexpr int Nn   = 4096;
constexpr int Sn   = 1024;
constexpr int MPTS = Bn * Nn;   // 65536
constexpr int MSRC = Bn * Sn;   // 16384
constexpr int CO   = 128;

// ---------------------------------------------------------------- scratch
__device__ __align__(16) float g_p2w[MSRC * CO];
__device__ __align__(16) float g_t0[(size_t)MPTS * CO];
__device__ __align__(16) float g_t1[(size_t)MPTS * CO];
__device__ __align__(16) float g_t2[(size_t)MPTS * CO];
__device__ __align__(16) int   g_idx[MPTS * 3];
__device__ __align__(16) float g_w[MPTS * 3];
__device__ __align__(16) float g_stats[3 * 256];   // zero-init at load; re-zeroed by knn3

__device__ __forceinline__ float gelu_exact(float x) {
    return 0.5f * x * (1.0f + erff(x * 0.70710678118654752440f));
}

__device__ __forceinline__ void split2(float a, float b, uint32_t& hi, uint32_t& lo) {
    __nv_bfloat16 ha = __float2bfloat16(a);
    __nv_bfloat16 hb = __float2bfloat16(b);
    __nv_bfloat16 la = __float2bfloat16(a - __bfloat162float(ha));
    __nv_bfloat16 lb = __float2bfloat16(b - __bfloat162float(hb));
    __nv_bfloat162 h; h.x = ha; h.y = hb;
    __nv_bfloat162 l; l.x = la; l.y = lb;
    hi = *reinterpret_cast<uint32_t*>(&h);
    lo = *reinterpret_cast<uint32_t*>(&l);
}

#define MMA16816(d, a, b0, b1)                                              \
    asm volatile(                                                           \
        "mma.sync.aligned.m16n8k16.row.col.f32.bf16.bf16.f32 "              \
        "{%0,%1,%2,%3}, {%4,%5,%6,%7}, {%8,%9}, {%0,%1,%2,%3};"             \
        : "+f"((d)[0]), "+f"((d)[1]), "+f"((d)[2]), "+f"((d)[3])            \
        : "r"((a)[0]), "r"((a)[1]), "r"((a)[2]), "r"((a)[3]),               \
          "r"(b0), "r"(b1))

// ---------------------------------------------------------------- small kernels
__global__ void knn3_kernel(const float* __restrict__ xyz1,
                            const float* __restrict__ xyz2,
                            int* __restrict__ gidx,
                            float* __restrict__ gw,
                            float* __restrict__ stats) {
    __shared__ float4 sp[Sn];
    const int b = blockIdx.x >> 5;
    const int n = ((blockIdx.x & 31) << 7) + threadIdx.x;

    if (blockIdx.x == 0) {
#pragma unroll
        for (int i = 0; i < 6; i++) stats[i * 128 + threadIdx.x] = 0.0f;
    }

    for (int s = threadIdx.x; s < Sn; s += 128) {
        const float* p = xyz2 + ((size_t)(b * Sn + s)) * 3;
        float x = p[0], y = p[1], z = p[2];
        sp[s] = make_float4(x, y, z, x * x + y * y + z * z);
    }
    __syncthreads();

    const int gi = b * Nn + n;
    const float* q = xyz1 + (size_t)gi * 3;
    const float x = q[0], y = q[1], z = q[2];
    const float n1 = x * x + y * y + z * z;

    float d0 = 3.4e38f, d1 = 3.4e38f, d2 = 3.4e38f;
    int   i0 = 0, i1 = 0, i2 = 0;
#pragma unroll 4
    for (int s = 0; s < Sn; s++) {
        float4 p = sp[s];
        float dot = fmaf(x, p.x, fmaf(y, p.y, z * p.z));
        float sq  = fmaf(-2.0f, dot, n1 + p.w);
        if (sq < d2) {
            if (sq < d1) {
                d2 = d1; i2 = i1;
                if (sq < d0) { d1 = d0; i1 = i0; d0 = sq; i0 = s; }
                else         { d1 = sq; i1 = s; }
            } else { d2 = sq; i2 = s; }
        }
    }
    float e0 = sqrtf(fmaxf(d0, 1e-12f));
    float e1 = sqrtf(fmaxf(d1, 1e-12f));
    float e2 = sqrtf(fmaxf(d2, 1e-12f));
    float r0 = 1.0f / (e0 + 1e-8f);
    float r1 = 1.0f / (e1 + 1e-8f);
    float r2 = 1.0f / (e2 + 1e-8f);
    float inv = 1.0f / (r0 + r1 + r2);
    gidx[gi * 3 + 0] = i0; gidx[gi * 3 + 1] = i1; gidx[gi * 3 + 2] = i2;
    gw[gi * 3 + 0] = r0 * inv; gw[gi * 3 + 1] = r1 * inv; gw[gi * 3 + 2] = r2 * inv;
}

__global__ void final_kernel(const float* __restrict__ t0,
                             const float* __restrict__ t2,
                             const float* __restrict__ st0,
                             const float* __restrict__ g0,
                             const float* __restrict__ bt0,
                             const float* __restrict__ st2,
                             const float* __restrict__ g2,
                             const float* __restrict__ bt2,
                             float* __restrict__ out) {
    __shared__ float s0[128], h0[128], s2[128], h2[128];
    int tid = threadIdx.x;
    if (tid < 128) {
        const float invM = 1.0f / (float)MPTS;
        float m0 = st0[tid] * invM;
        float v0 = st0[128 + tid] * invM - m0 * m0;
        float sc0 = g0[tid] * rsqrtf(v0 + 1e-5f);
        s0[tid] = sc0; h0[tid] = fmaf(-m0, sc0, bt0[tid]);
        float m2 = st2[tid] * invM;
        float v2 = st2[128 + tid] * invM - m2 * m2;
        float sc2 = g2[tid] * rsqrtf(v2 + 1e-5f);
        s2[tid] = sc2; h2[tid] = fmaf(-m2, sc2, bt2[tid]);
    }
    __syncthreads();
    size_t i4 = (size_t)blockIdx.x * blockDim.x + tid;
    float4 a = reinterpret_cast<const float4*>(t0)[i4];
    float4 b = reinterpret_cast<const float4*>(t2)[i4];
    int c = (int)(i4 & 31) << 2;
    float x0 = gelu_exact(fmaf(s0[c + 0], a.x, h0[c + 0]));
    float x1 = gelu_exact(fmaf(s0[c + 1], a.y, h0[c + 1]));
    float x2 = gelu_exact(fmaf(s0[c + 2], a.z, h0[c + 2]));
    float x3 = gelu_exact(fmaf(s0[c + 3], a.w, h0[c + 3]));
    float y0 = fmaf(s2[c + 0], b.x, h2[c + 0]) + x0;
    float y1 = fmaf(s2[c + 1], b.y, h2[c + 1]) + x1;
    float y2 = fmaf(s2[c + 2], b.z, h2[c + 2]) + x2;
    float y3 = fmaf(s2[c + 3], b.w, h2[c + 3]) + x3;
    reinterpret_cast<float4*>(out)[i4] =
        make_float4(gelu_exact(y0), gelu_exact(y1), gelu_exact(y2), gelu_exact(y3));
}

// ---------------------------------------------------------------- HMMA GEMM
// out[m,0:128] = op(A[m,0:KDIM]) @ W[0:128,0:KDIM]^T (+bias)(+gather)(+stats)
// bf16 split-3 via mma.sync m16n8k16. A fragments loaded DIRECTLY from global
// (float2 per fragment word), converted in registers — no A smem, no k-loop
// barriers. W lives in smem (hi/lo, k/k+8 interleaved) and is read-only.
template <int KDIM, bool PRO, bool GATHER, bool STATS>
__global__ __launch_bounds__(256, 2)
void mma_gemm(const float* __restrict__ A,
              const float* __restrict__ W, int wstride,
              const float* __restrict__ bias,
              float* __restrict__ out,
              const float* __restrict__ stats_in,  // prev layer sums (PRO)
              const float* __restrict__ gamma,
              const float* __restrict__ beta,
              float* __restrict__ stats,           // this layer sums (STATS)
              const int* __restrict__ gidx,
              const float* __restrict__ gw,
              const float* __restrict__ p2w,
              int ntiles) {
    extern __shared__ char sm[];
    constexpr int WROW = 4 * KDIM + 32;   // [hi 2K][lo 2K][pad 32]
    constexpr int WLO  = 2 * KDIM;
    constexpr int AUX  = 128 * WROW;
    constexpr int NKS  = KDIM / 16;

    float* sBias = reinterpret_cast<float*>(sm + AUX);
    float* sAff  = reinterpret_cast<float*>(sm + AUX + 512);
    float* sSum  = reinterpret_cast<float*>(sm + AUX + 1536);
    float* sSq   = reinterpret_cast<float*>(sm + AUX + 2048);

    const int tid  = threadIdx.x;
    const int lane = tid & 31;
    const int w    = tid >> 5;
    const int wm   = w & 3;
    const int wn   = w >> 2;
    const int lg   = lane >> 2;
    const int lq   = lane & 3;

    if (tid < 128) {
        sBias[tid] = bias ? bias[tid] : 0.0f;
        if (STATS) { sSum[tid] = 0.0f; sSq[tid] = 0.0f; }
        if (PRO) {
            const float invM = 1.0f / (float)MPTS;
            float mean = stats_in[tid] * invM;
            float var  = stats_in[128 + tid] * invM - mean * mean;
            float sc   = gamma[tid] * rsqrtf(var + 1e-5f);
            sAff[tid]       = sc;
            sAff[128 + tid] = fmaf(-mean, sc, beta[tid]);
        }
    }

    // ---- W -> smem bf16 hi/lo, k/k+8 interleaved within 16-k blocks ----
    for (int idx = tid; idx < 128 * KDIM; idx += 256) {
        int n = idx / KDIM, k = idx % KDIM;
        float v = W[n * wstride + k];
        __nv_bfloat16 h = __float2bfloat16(v);
        __nv_bfloat16 l = __float2bfloat16(v - __bfloat162float(h));
        int kk  = k & 15;
        int pos = ((kk & 7) >> 1) * 8 + ((kk >> 3) & 1) * 4 + (kk & 1) * 2;
        int off = n * WROW + (k >> 4) * 32 + pos;
        *reinterpret_cast<__nv_bfloat16*>(sm + off)       = h;
        *reinterpret_cast<__nv_bfloat16*>(sm + off + WLO) = l;
    }
    __syncthreads();

    for (int t = blockIdx.x; t < ntiles; t += gridDim.x) {
        const float* Abase = A + (size_t)t * 128 * KDIM;

        float acc[2][8][4];
#pragma unroll
        for (int mi = 0; mi < 2; mi++)
#pragma unroll
            for (int nf = 0; nf < 8; nf++)
#pragma unroll
                for (int r = 0; r < 4; r++) acc[mi][nf][r] = 0.0f;

#pragma unroll
        for (int ks = 0; ks < NKS; ks++) {
            const int c0 = ks * 16 + lq * 2;   // k channels for a0/a1
            const int c1 = c0 + 8;             // k channels for a2/a3

            float2 s0, h0, s1, h1;
            if (PRO) {
                s0 = *reinterpret_cast<const float2*>(&sAff[c0]);
                h0 = *reinterpret_cast<const float2*>(&sAff[128 + c0]);
                s1 = *reinterpret_cast<const float2*>(&sAff[c1]);
                h1 = *reinterpret_cast<const float2*>(&sAff[128 + c1]);
            }

            uint32_t ah[2][4], al[2][4];
#pragma unroll
            for (int mi = 0; mi < 2; mi++) {
                const float* pr0 = Abase + (size_t)(wm * 32 + mi * 16 + lg) * KDIM;
                const float* pr1 = pr0 + 8 * KDIM;
                float2 f0 = *reinterpret_cast<const float2*>(pr0 + c0);
                float2 f1 = *reinterpret_cast<const float2*>(pr1 + c0);
                float2 f2 = *reinterpret_cast<const float2*>(pr0 + c1);
                float2 f3 = *reinterpret_cast<const float2*>(pr1 + c1);
                if (PRO) {
                    f0.x = gelu_exact(fmaf(s0.x, f0.x, h0.x));
                    f0.y = gelu_exact(fmaf(s0.y, f0.y, h0.y));
                    f1.x = gelu_exact(fmaf(s0.x, f1.x, h0.x));
                    f1.y = gelu_exact(fmaf(s0.y, f1.y, h0.y));
                    f2.x = gelu_exact(fmaf(s1.x, f2.x, h1.x));
                    f2.y = gelu_exact(fmaf(s1.y, f2.y, h1.y));
                    f3.x = gelu_exact(fmaf(s1.x, f3.x, h1.x));
                    f3.y = gelu_exact(fmaf(s1.y, f3.y, h1.y));
                }
                split2(f0.x, f0.y, ah[mi][0], al[mi][0]);
                split2(f1.x, f1.y, ah[mi][1], al[mi][1]);
                split2(f2.x, f2.y, ah[mi][2], al[mi][2]);
                split2(f3.x, f3.y, ah[mi][3], al[mi][3]);
            }

#pragma unroll
            for (int nf = 0; nf < 8; nf++) {
                const char* pw = sm + (wn * 64 + nf * 8 + lg) * WROW +
                                 ks * 32 + lq * 8;
                uint2 bh = *reinterpret_cast<const uint2*>(pw);
                uint2 bl = *reinterpret_cast<const uint2*>(pw + WLO);
#pragma unroll
                for (int mi = 0; mi < 2; mi++) {
                    MMA16816(acc[mi][nf], ah[mi], bh.x, bh.y);
                    MMA16816(acc[mi][nf], al[mi], bh.x, bh.y);
                    MMA16816(acc[mi][nf], ah[mi], bl.x, bl.y);
                }
            }
        }

        // ---- epilogue: bias (+gather), store, stats ----
        float cS[16], cQ[16];
        if (STATS) {
#pragma unroll
            for (int i = 0; i < 16; i++) { cS[i] = 0.0f; cQ[i] = 0.0f; }
        }
#pragma unroll
        for (int mi = 0; mi < 2; mi++) {
#pragma unroll
            for (int rh = 0; rh < 2; rh++) {
                int r = wm * 32 + mi * 16 + rh * 8 + lg;
                int m = t * 128 + r;
                int j0 = 0, j1 = 0, j2 = 0, gb = 0;
                float w0 = 0.f, w1 = 0.f, w2 = 0.f;
                if (GATHER) {
                    j0 = gidx[3 * m + 0]; j1 = gidx[3 * m + 1]; j2 = gidx[3 * m + 2];
                    w0 = gw[3 * m + 0];   w1 = gw[3 * m + 1];   w2 = gw[3 * m + 2];
                    gb = (m >> 12) << 17;
                }
                float* orow = out + (size_t)m * 128;
#pragma unroll
                for (int nf = 0; nf < 8; nf++) {
                    int c0 = wn * 64 + nf * 8 + lq * 2;
                    float v0 = acc[mi][nf][rh * 2 + 0] + sBias[c0];
                    float v1 = acc[mi][nf][rh * 2 + 1] + sBias[c0 + 1];
                    if (GATHER) {
                        float2 a0 = *reinterpret_cast<const float2*>(p2w + gb + (j0 << 7) + c0);
                        float2 a1 = *reinterpret_cast<const float2*>(p2w + gb + (j1 << 7) + c0);
                        float2 a2 = *reinterpret_cast<const float2*>(p2w + gb + (j2 << 7) + c0);
                        v0 += w0 * a0.x + w1 * a1.x + w2 * a2.x;
                        v1 += w0 * a0.y + w1 * a1.y + w2 * a2.y;
                    }
                    *reinterpret_cast<float2*>(orow + c0) = make_float2(v0, v1);
                    if (STATS) {
                        cS[nf * 2 + 0] += v0;
                        cS[nf * 2 + 1] += v1;
                        cQ[nf * 2 + 0] = fmaf(v0, v0, cQ[nf * 2 + 0]);
                        cQ[nf * 2 + 1] = fmaf(v1, v1, cQ[nf * 2 + 1]);
                    }
                }
            }
        }
        if (STATS) {
#pragma unroll
            for (int i = 0; i < 16; i++) {
                cS[i] += __shfl_xor_sync(0xffffffffu, cS[i], 4);
                cQ[i] += __shfl_xor_sync(0xffffffffu, cQ[i], 4);
                cS[i] += __shfl_xor_sync(0xffffffffu, cS[i], 8);
                cQ[i] += __shfl_xor_sync(0xffffffffu, cQ[i], 8);
                cS[i] += __shfl_xor_sync(0xffffffffu, cS[i], 16);
                cQ[i] += __shfl_xor_sync(0xffffffffu, cQ[i], 16);
            }
            if (lane < 4) {
#pragma unroll
                for (int nf = 0; nf < 8; nf++) {
                    int c = wn * 64 + nf * 8 + lane * 2;
                    atomicAdd(&sSum[c],     cS[nf * 2 + 0]);
                    atomicAdd(&sSum[c + 1], cS[nf * 2 + 1]);
                    atomicAdd(&sSq[c],      cQ[nf * 2 + 0]);
                    atomicAdd(&sSq[c + 1],  cQ[nf * 2 + 1]);
                }
            }
        }
    }

    if (STATS) {
        __syncthreads();
        if (tid < 128) {
            atomicAdd(&stats[tid],       sSum[tid]);
            atomicAdd(&stats[128 + tid], sSq[tid]);
        }
    }
}

// ---------------------------------------------------------------- launch
extern "C" void kernel_launch(void* const* d_in, const int* in_sizes, int n_in,
                              void* d_out, int out_size) {
    const float* xyz1    = (const float*)d_in[0];
    const float* xyz2    = (const float*)d_in[1];
    const float* points1 = (const float*)d_in[2];
    const float* points2 = (const float*)d_in[3];
    const float* fuse_w  = (const float*)d_in[4];
    const float* fuse_b  = (const float*)d_in[5];
    const float* fuse_g  = (const float*)d_in[6];
    const float* fuse_bt = (const float*)d_in[7];
    const float* w1      = (const float*)d_in[8];
    const float* b1      = (const float*)d_in[9];
    const float* g1      = (const float*)d_in[10];
    const float* bt1     = (const float*)d_in[11];
    const float* w2      = (const float*)d_in[12];
    const float* b2      = (const float*)d_in[13];
    const float* g2      = (const float*)d_in[14];
    const float* bt2     = (const float*)d_in[15];
    float* out = (float*)d_out;

    float *p_p2w, *p_t0, *p_t1, *p_t2, *p_w, *p_stats;
    int* p_idx;
    cudaGetSymbolAddress((void**)&p_p2w,   g_p2w);
    cudaGetSymbolAddress((void**)&p_t0,    g_t0);
    cudaGetSymbolAddress((void**)&p_t1,    g_t1);
    cudaGetSymbolAddress((void**)&p_t2,    g_t2);
    cudaGetSymbolAddress((void**)&p_idx,   g_idx);
    cudaGetSymbolAddress((void**)&p_w,     g_w);
    cudaGetSymbolAddress((void**)&p_stats, g_stats);

    // dyn smem: W(128*WROW) + 2560 aux
    constexpr int SMEM_K128 = 128 * (4 * 128 + 32) + 2560;  // 72192
    constexpr int SMEM_K256 = 128 * (4 * 256 + 32) + 2560;  // 137728
    static bool attr_done = false;
    if (!attr_done) {
        cudaFuncSetAttribute(mma_gemm<256, false, false, false>,
                             cudaFuncAttributeMaxDynamicSharedMemorySize, SMEM_K256);
        cudaFuncSetAttribute(mma_gemm<128, false, true, true>,
                             cudaFuncAttributeMaxDynamicSharedMemorySize, SMEM_K128);
        cudaFuncSetAttribute(mma_gemm<128, true, false, true>,
                             cudaFuncAttributeMaxDynamicSharedMemorySize, SMEM_K128);
        attr_done = true;
    }

    // knn + stat zeroing
    knn3_kernel<<<Bn * 32, 128>>>(xyz1, xyz2, p_idx, p_w, p_stats);

    // P2W = points2 @ fuse_w[:,128:384]^T   (16384 x 128, K=256)
    mma_gemm<256, false, false, false><<<MSRC / 128, 256, SMEM_K256>>>(
        points2, fuse_w + 128, 384, nullptr, p_p2w,
        nullptr, nullptr, nullptr, nullptr, nullptr, nullptr, nullptr, MSRC / 128);

    // t0 = points1 @ fuse_w[:,0:128]^T + fuse_b + gather(P2W) ; stats0
    mma_gemm<128, false, true, true><<<296, 256, SMEM_K128>>>(
        points1, fuse_w, 384, fuse_b, p_t0,
        nullptr, nullptr, nullptr, p_stats + 0, p_idx, p_w, p_p2w, MPTS / 128);

    // t1 = gelu(bn0(t0)) @ w1^T + b1 ; stats1   (aff computed in-kernel)
    mma_gemm<128, true, false, true><<<296, 256, SMEM_K128>>>(
        p_t0, w1, 128, b1, p_t1,
        p_stats + 0, fuse_g, fuse_bt, p_stats + 256, nullptr, nullptr, nullptr, MPTS / 128);

    // t2 = gelu(bn1(t1)) @ w2^T + b2 ; stats2
    mma_gemm<128, true, false, true><<<296, 256, SMEM_K128>>>(
        p_t1, w2, 128, b2, p_t2,
        p_stats + 256, g1, bt1, p_stats + 512, nullptr, nullptr, nullptr, MPTS / 128);

    // out = gelu(bn2(t2) + gelu(bn0(t0)))  (both affines computed in-kernel)
    final_kernel<<<(MPTS * 128 / 4) / 256, 256>>>(
        p_t0, p_t2, p_stats + 0, fuse_g, fuse_bt, p_stats + 512, g2, bt2, out);
}

// round 16
// speedup vs baseline: 1.5349x; 1.5349x over previous
#include <cuda_runtime.h>
#include <cuda_bf16.h>
#include <math.h>
#include <stdint.h>

// ---------------------------------------------------------------- constants
constexpr int Bn   = 16;
constexpr int Nn   = 4096;
constexpr int Sn   = 1024;
constexpr int MPTS = Bn * Nn;   // 65536
constexpr int MSRC = Bn * Sn;   // 16384
constexpr int CO   = 128;

// ---------------------------------------------------------------- scratch
__device__ __align__(16) float g_p2w[MSRC * CO];
__device__ __align__(16) float g_t0[(size_t)MPTS * CO];
__device__ __align__(16) float g_t1[(size_t)MPTS * CO];
__device__ __align__(16) float g_t2[(size_t)MPTS * CO];
__device__ __align__(16) int   g_idx[MPTS * 3];
__device__ __align__(16) float g_w[MPTS * 3];
__device__ __align__(16) float g_stats[3 * 256];   // zero-init at load; re-zeroed by knn3

__device__ __forceinline__ float gelu_exact(float x) {
    return 0.5f * x * (1.0f + erff(x * 0.70710678118654752440f));
}

// fast split: hi = truncate-to-bf16 (PRMT pack), lo = exact residual (RN bf16x2)
__device__ __forceinline__ void split2(float a, float b, uint32_t& hi, uint32_t& lo) {
    uint32_t ua = __float_as_uint(a), ub = __float_as_uint(b);
    asm("prmt.b32 %0, %1, %2, 0x7632;" : "=r"(hi) : "r"(ua), "r"(ub));
    float la = a - __uint_as_float(ua & 0xffff0000u);
    float lb = b - __uint_as_float(ub & 0xffff0000u);
    asm("cvt.rn.bf16x2.f32 %0, %1, %2;" : "=r"(lo) : "f"(lb), "f"(la));
}

__device__ __forceinline__ uint32_t smem_u32(const void* p) {
    uint32_t a;
    asm("{ .reg .u64 t; cvta.to.shared.u64 t, %1; cvt.u32.u64 %0, t; }"
        : "=r"(a) : "l"(p));
    return a;
}

#define MMA16816(d, a, b0, b1)                                              \
    asm volatile(                                                           \
        "mma.sync.aligned.m16n8k16.row.col.f32.bf16.bf16.f32 "              \
        "{%0,%1,%2,%3}, {%4,%5,%6,%7}, {%8,%9}, {%0,%1,%2,%3};"             \
        : "+f"((d)[0]), "+f"((d)[1]), "+f"((d)[2]), "+f"((d)[3])            \
        : "r"((a)[0]), "r"((a)[1]), "r"((a)[2]), "r"((a)[3]),               \
          "r"(b0), "r"(b1))

#define LDMX4(r, addr)                                                      \
    asm volatile(                                                           \
        "ldmatrix.sync.aligned.m8n8.x4.shared.b16 {%0,%1,%2,%3}, [%4];"     \
        : "=r"((r)[0]), "=r"((r)[1]), "=r"((r)[2]), "=r"((r)[3])            \
        : "r"(addr))

#define BAR_PAIR(id)                                                        \
    asm volatile("bar.sync %0, %1;" :: "r"(id), "r"(64) : "memory")

// ---------------------------------------------------------------- small kernels
__global__ void knn3_kernel(const float* __restrict__ xyz1,
                            const float* __restrict__ xyz2,
                            int* __restrict__ gidx,
                            float* __restrict__ gw,
                            float* __restrict__ stats) {
    __shared__ float4 sp[Sn];
    const int b = blockIdx.x >> 5;
    const int n = ((blockIdx.x & 31) << 7) + threadIdx.x;

    if (blockIdx.x == 0) {
#pragma unroll
        for (int i = 0; i < 6; i++) stats[i * 128 + threadIdx.x] = 0.0f;
    }

    for (int s = threadIdx.x; s < Sn; s += 128) {
        const float* p = xyz2 + ((size_t)(b * Sn + s)) * 3;
        float x = p[0], y = p[1], z = p[2];
        sp[s] = make_float4(x, y, z, x * x + y * y + z * z);
    }
    __syncthreads();

    const int gi = b * Nn + n;
    const float* q = xyz1 + (size_t)gi * 3;
    const float x = q[0], y = q[1], z = q[2];
    const float n1 = x * x + y * y + z * z;

    float d0 = 3.4e38f, d1 = 3.4e38f, d2 = 3.4e38f;
    int   i0 = 0, i1 = 0, i2 = 0;
#pragma unroll 4
    for (int s = 0; s < Sn; s++) {
        float4 p = sp[s];
        float dot = fmaf(x, p.x, fmaf(y, p.y, z * p.z));
        float sq  = fmaf(-2.0f, dot, n1 + p.w);
        if (sq < d2) {
            if (sq < d1) {
                d2 = d1; i2 = i1;
                if (sq < d0) { d1 = d0; i1 = i0; d0 = sq; i0 = s; }
                else         { d1 = sq; i1 = s; }
            } else { d2 = sq; i2 = s; }
        }
    }
    float e0 = sqrtf(fmaxf(d0, 1e-12f));
    float e1 = sqrtf(fmaxf(d1, 1e-12f));
    float e2 = sqrtf(fmaxf(d2, 1e-12f));
    float r0 = 1.0f / (e0 + 1e-8f);
    float r1 = 1.0f / (e1 + 1e-8f);
    float r2 = 1.0f / (e2 + 1e-8f);
    float inv = 1.0f / (r0 + r1 + r2);
    gidx[gi * 3 + 0] = i0; gidx[gi * 3 + 1] = i1; gidx[gi * 3 + 2] = i2;
    gw[gi * 3 + 0] = r0 * inv; gw[gi * 3 + 1] = r1 * inv; gw[gi * 3 + 2] = r2 * inv;
}

__global__ void final_kernel(const float* __restrict__ t0,
                             const float* __restrict__ t2,
                             const float* __restrict__ st0,
                             const float* __restrict__ g0,
                             const float* __restrict__ bt0,
                             const float* __restrict__ st2,
                             const float* __restrict__ g2,
                             const float* __restrict__ bt2,
                             float* __restrict__ out) {
    __shared__ float s0[128], h0[128], s2[128], h2[128];
    int tid = threadIdx.x;
    if (tid < 128) {
        const float invM = 1.0f / (float)MPTS;
        float m0 = st0[tid] * invM;
        float v0 = st0[128 + tid] * invM - m0 * m0;
        float sc0 = g0[tid] * rsqrtf(v0 + 1e-5f);
        s0[tid] = sc0; h0[tid] = fmaf(-m0, sc0, bt0[tid]);
        float m2 = st2[tid] * invM;
        float v2 = st2[128 + tid] * invM - m2 * m2;
        float sc2 = g2[tid] * rsqrtf(v2 + 1e-5f);
        s2[tid] = sc2; h2[tid] = fmaf(-m2, sc2, bt2[tid]);
    }
    __syncthreads();
    size_t i4 = (size_t)blockIdx.x * blockDim.x + tid;
    float4 a = reinterpret_cast<const float4*>(t0)[i4];
    float4 b = reinterpret_cast<const float4*>(t2)[i4];
    int c = (int)(i4 & 31) << 2;
    float x0 = gelu_exact(fmaf(s0[c + 0], a.x, h0[c + 0]));
    float x1 = gelu_exact(fmaf(s0[c + 1], a.y, h0[c + 1]));
    float x2 = gelu_exact(fmaf(s0[c + 2], a.z, h0[c + 2]));
    float x3 = gelu_exact(fmaf(s0[c + 3], a.w, h0[c + 3]));
    float y0 = fmaf(s2[c + 0], b.x, h2[c + 0]) + x0;
    float y1 = fmaf(s2[c + 1], b.y, h2[c + 1]) + x1;
    float y2 = fmaf(s2[c + 2], b.z, h2[c + 2]) + x2;
    float y3 = fmaf(s2[c + 3], b.w, h2[c + 3]) + x3;
    reinterpret_cast<float4*>(out)[i4] =
        make_float4(gelu_exact(y0), gelu_exact(y1), gelu_exact(y2), gelu_exact(y3));
}

// ---------------------------------------------------------------- HMMA GEMM
// out[m,0:128] = op(A[m,0:KDIM]) @ W[0:128,0:KDIM]^T (+bias)(+gather)(+stats)
// bf16 split-3; 2 CTAs/SM; per-warp-pair staging + 64-thread named barriers;
// fast trunc-split conversion; BN affine computed in-kernel from raw stats.
template <int KDIM, bool PRO, bool GATHER, bool STATS>
__global__ __launch_bounds__(256, 2)
void mma_gemm(const float* __restrict__ A,
              const float* __restrict__ W, int wstride,
              const float* __restrict__ bias,
              float* __restrict__ out,
              const float* __restrict__ stats_in,  // prev layer sums (PRO)
              const float* __restrict__ gamma,
              const float* __restrict__ beta,
              float* __restrict__ stats,           // this layer sums (STATS)
              const int* __restrict__ gidx,
              const float* __restrict__ gw,
              const float* __restrict__ p2w,
              int ntiles) {
    extern __shared__ char sm[];
    constexpr int WROW   = 4 * KDIM + 32;   // [hi 2K][lo 2K][pad 32]
    constexpr int WLO    = 2 * KDIM;
    constexpr int OFF_A  = 128 * WROW;
    constexpr int APITCH = 80;
    constexpr int ALO    = 128 * APITCH;    // 10240
    constexpr int ABUF   = 2 * ALO;         // 20480 (hi+lo per buffer)
    constexpr int AUX    = OFF_A + 2 * ABUF;
    constexpr int NCH    = KDIM / 32;

    float* sBias = reinterpret_cast<float*>(sm + AUX);
    float* sAff  = reinterpret_cast<float*>(sm + AUX + 512);
    float* sSum  = reinterpret_cast<float*>(sm + AUX + 1536);
    float* sSq   = reinterpret_cast<float*>(sm + AUX + 2048);

    const int tid  = threadIdx.x;
    const int lane = tid & 31;
    const int w    = tid >> 5;
    const int wm   = w & 3;
    const int wn   = w >> 2;
    const int lg   = lane >> 2;
    const int lq   = lane & 3;
    const uint32_t sbase = smem_u32(sm);

    if (tid < 128) {
        sBias[tid] = bias ? bias[tid] : 0.0f;
        if (STATS) { sSum[tid] = 0.0f; sSq[tid] = 0.0f; }
        if (PRO) {
            const float invM = 1.0f / (float)MPTS;
            float mean = stats_in[tid] * invM;
            float var  = stats_in[128 + tid] * invM - mean * mean;
            float sc   = gamma[tid] * rsqrtf(var + 1e-5f);
            sAff[tid]       = sc;
            sAff[128 + tid] = fmaf(-mean, sc, beta[tid]);
        }
    }

    // ---- W -> smem bf16 hi/lo, k/k+8 interleaved within 16-k blocks ----
    for (int idx = tid; idx < 128 * KDIM; idx += 256) {
        int n = idx / KDIM, k = idx % KDIM;
        float v = W[n * wstride + k];
        uint32_t uv = __float_as_uint(v);
        float lres = v - __uint_as_float(uv & 0xffff0000u);
        uint16_t hbits = (uint16_t)(uv >> 16);
        __nv_bfloat16 l = __float2bfloat16(lres);
        int kk  = k & 15;
        int pos = ((kk & 7) >> 1) * 8 + ((kk >> 3) & 1) * 4 + (kk & 1) * 2;
        int off = n * WROW + (k >> 4) * 32 + pos;
        *reinterpret_cast<uint16_t*>(sm + off)            = hbits;
        *reinterpret_cast<__nv_bfloat16*>(sm + off + WLO) = l;
    }
    __syncthreads();

    // pair-local staging map: warps {wm, wm+4} own rows [wm*32, wm*32+32)
    const int pt   = wn * 32 + lane;        // 0..63 within the pair
    const int prow = wm * 32 + (pt >> 1);   // row this thread stages
    const int pq0  = (pt & 1) * 4;          // first 4-float quad (of 8)

    for (int t = blockIdx.x; t < ntiles; t += gridDim.x) {
        const float* Abase = A + (size_t)t * 128 * KDIM;

        float acc[2][8][4];
#pragma unroll
        for (int mi = 0; mi < 2; mi++)
#pragma unroll
            for (int nf = 0; nf < 8; nf++)
#pragma unroll
                for (int r = 0; r < 4; r++) acc[mi][nf][r] = 0.0f;

        // prefetch chunk 0
        float4 pf[4];
#pragma unroll
        for (int q = 0; q < 4; q++)
            pf[q] = *reinterpret_cast<const float4*>(
                Abase + (size_t)prow * KDIM + (pq0 + q) * 4);

        for (int kc = 0; kc < NCH; kc++) {
            const int bufo = OFF_A + (kc & 1) * ABUF;
            // ---- convert own rows -> smem bf16 hi/lo (buffer kc&1) ----
#pragma unroll
            for (int q = 0; q < 4; q++) {
                float4 f = pf[q];
                if (PRO) {
                    int c = kc * 32 + (pq0 + q) * 4;
                    f.x = gelu_exact(fmaf(sAff[c + 0], f.x, sAff[128 + c + 0]));
                    f.y = gelu_exact(fmaf(sAff[c + 1], f.y, sAff[128 + c + 1]));
                    f.z = gelu_exact(fmaf(sAff[c + 2], f.z, sAff[128 + c + 2]));
                    f.w = gelu_exact(fmaf(sAff[c + 3], f.w, sAff[128 + c + 3]));
                }
                uint32_t h0, l0, h1, l1;
                split2(f.x, f.y, h0, l0);
                split2(f.z, f.w, h1, l1);
                char* b = sm + bufo + prow * APITCH + (pq0 + q) * 8;
                *reinterpret_cast<uint2*>(b)       = make_uint2(h0, h1);
                *reinterpret_cast<uint2*>(b + ALO) = make_uint2(l0, l1);
            }
            BAR_PAIR(wm + 1);   // only the 2 warps sharing these rows sync

            // ---- issue next chunk's loads (hidden under MMA) ----
            if (kc + 1 < NCH) {
#pragma unroll
                for (int q = 0; q < 4; q++)
                    pf[q] = *reinterpret_cast<const float4*>(
                        Abase + (size_t)prow * KDIM + (kc + 1) * 32 + (pq0 + q) * 4);
            }

            // ---- MMA on current buffer (rows wm*32..+32 only) ----
            const uint32_t abase = sbase + bufo;
            const uint32_t lrow  = lane & 15;
            const uint32_t lkb   = (lane >> 4) << 4;
#pragma unroll
            for (int ks = 0; ks < 2; ks++) {
                uint32_t ah[2][4], al[2][4];
#pragma unroll
                for (int mi = 0; mi < 2; mi++) {
                    uint32_t ad = abase +
                        (wm * 32 + mi * 16 + lrow) * APITCH + ks * 32 + lkb;
                    LDMX4(ah[mi], ad);
                    LDMX4(al[mi], ad + ALO);
                }
#pragma unroll
                for (int nf = 0; nf < 8; nf++) {
                    const char* pw = sm + (wn * 64 + nf * 8 + lg) * WROW +
                                     (kc * 2 + ks) * 32 + lq * 8;
                    uint2 bh = *reinterpret_cast<const uint2*>(pw);
                    uint2 bl = *reinterpret_cast<const uint2*>(pw + WLO);
#pragma unroll
                    for (int mi = 0; mi < 2; mi++) {
                        MMA16816(acc[mi][nf], ah[mi], bh.x, bh.y);
                        MMA16816(acc[mi][nf], al[mi], bh.x, bh.y);
                        MMA16816(acc[mi][nf], ah[mi], bl.x, bl.y);
                    }
                }
            }
            // next convert writes the other buffer; pair barrier orders reuse
        }

        // ---- epilogue: bias (+gather), store, stats ----
        float cS[16], cQ[16];
        if (STATS) {
#pragma unroll
            for (int i = 0; i < 16; i++) { cS[i] = 0.0f; cQ[i] = 0.0f; }
        }
#pragma unroll
        for (int mi = 0; mi < 2; mi++) {
#pragma unroll
            for (int rh = 0; rh < 2; rh++) {
                int r = wm * 32 + mi * 16 + rh * 8 + lg;
                int m = t * 128 + r;
                int j0 = 0, j1 = 0, j2 = 0, gb = 0;
                float w0 = 0.f, w1 = 0.f, w2 = 0.f;
                if (GATHER) {
                    j0 = gidx[3 * m + 0]; j1 = gidx[3 * m + 1]; j2 = gidx[3 * m + 2];
                    w0 = gw[3 * m + 0];   w1 = gw[3 * m + 1];   w2 = gw[3 * m + 2];
                    gb = (m >> 12) << 17;
                }
                float* orow = out + (size_t)m * 128;
#pragma unroll
                for (int nf = 0; nf < 8; nf++) {
                    int c0 = wn * 64 + nf * 8 + lq * 2;
                    float v0 = acc[mi][nf][rh * 2 + 0] + sBias[c0];
                    float v1 = acc[mi][nf][rh * 2 + 1] + sBias[c0 + 1];
                    if (GATHER) {
                        float2 a0 = *reinterpret_cast<const float2*>(p2w + gb + (j0 << 7) + c0);
                        float2 a1 = *reinterpret_cast<const float2*>(p2w + gb + (j1 << 7) + c0);
                        float2 a2 = *reinterpret_cast<const float2*>(p2w + gb + (j2 << 7) + c0);
                        v0 += w0 * a0.x + w1 * a1.x + w2 * a2.x;
                        v1 += w0 * a0.y + w1 * a1.y + w2 * a2.y;
                    }
                    *reinterpret_cast<float2*>(orow + c0) = make_float2(v0, v1);
                    if (STATS) {
                        cS[nf * 2 + 0] += v0;
                        cS[nf * 2 + 1] += v1;
                        cQ[nf * 2 + 0] = fmaf(v0, v0, cQ[nf * 2 + 0]);
                        cQ[nf * 2 + 1] = fmaf(v1, v1, cQ[nf * 2 + 1]);
                    }
                }
            }
        }
        if (STATS) {
#pragma unroll
            for (int i = 0; i < 16; i++) {
                cS[i] += __shfl_xor_sync(0xffffffffu, cS[i], 4);
                cQ[i] += __shfl_xor_sync(0xffffffffu, cQ[i], 4);
                cS[i] += __shfl_xor_sync(0xffffffffu, cS[i], 8);
                cQ[i] += __shfl_xor_sync(0xffffffffu, cQ[i], 8);
                cS[i] += __shfl_xor_sync(0xffffffffu, cS[i], 16);
                cQ[i] += __shfl_xor_sync(0xffffffffu, cQ[i], 16);
            }
            if (lane < 4) {
#pragma unroll
                for (int nf = 0; nf < 8; nf++) {
                    int c = wn * 64 + nf * 8 + lane * 2;
                    atomicAdd(&sSum[c],     cS[nf * 2 + 0]);
                    atomicAdd(&sSum[c + 1], cS[nf * 2 + 1]);
                    atomicAdd(&sSq[c],      cQ[nf * 2 + 0]);
                    atomicAdd(&sSq[c + 1],  cQ[nf * 2 + 1]);
                }
            }
        }
    }

    if (STATS) {
        __syncthreads();
        if (tid < 128) {
            atomicAdd(&stats[tid],       sSum[tid]);
            atomicAdd(&stats[128 + tid], sSq[tid]);
        }
    }
}

// ---------------------------------------------------------------- launch
extern "C" void kernel_launch(void* const* d_in, const int* in_sizes, int n_in,
                              void* d_out, int out_size) {
    const float* xyz1    = (const float*)d_in[0];
    const float* xyz2    = (const float*)d_in[1];
    const float* points1 = (const float*)d_in[2];
    const float* points2 = (const float*)d_in[3];
    const float* fuse_w  = (const float*)d_in[4];
    const float* fuse_b  = (const float*)d_in[5];
    const float* fuse_g  = (const float*)d_in[6];
    const float* fuse_bt = (const float*)d_in[7];
    const float* w1      = (const float*)d_in[8];
    const float* b1      = (const float*)d_in[9];
    const float* g1      = (const float*)d_in[10];
    const float* bt1     = (const float*)d_in[11];
    const float* w2      = (const float*)d_in[12];
    const float* b2      = (const float*)d_in[13];
    const float* g2      = (const float*)d_in[14];
    const float* bt2     = (const float*)d_in[15];
    float* out = (float*)d_out;

    float *p_p2w, *p_t0, *p_t1, *p_t2, *p_w, *p_stats;
    int* p_idx;
    cudaGetSymbolAddress((void**)&p_p2w,   g_p2w);
    cudaGetSymbolAddress((void**)&p_t0,    g_t0);
    cudaGetSymbolAddress((void**)&p_t1,    g_t1);
    cudaGetSymbolAddress((void**)&p_t2,    g_t2);
    cudaGetSymbolAddress((void**)&p_idx,   g_idx);
    cudaGetSymbolAddress((void**)&p_w,     g_w);
    cudaGetSymbolAddress((void**)&p_stats, g_stats);

    // dyn smem: W(128*WROW) + 2 A buffers + 2560 aux
    constexpr int SMEM_K128 = 128 * (4 * 128 + 32) + 2 * 20480 + 2560;  // 113152
    constexpr int SMEM_K256 = 128 * (4 * 256 + 32) + 2 * 20480 + 2560;  // 178688
    static bool attr_done = false;
    if (!attr_done) {
        cudaFuncSetAttribute(mma_gemm<256, false, false, false>,
                             cudaFuncAttributeMaxDynamicSharedMemorySize, SMEM_K256);
        cudaFuncSetAttribute(mma_gemm<128, false, true, true>,
                             cudaFuncAttributeMaxDynamicSharedMemorySize, SMEM_K128);
        cudaFuncSetAttribute(mma_gemm<128, true, false, true>,
                             cudaFuncAttributeMaxDynamicSharedMemorySize, SMEM_K128);
        attr_done = true;
    }

    // knn + stat zeroing
    knn3_kernel<<<Bn * 32, 128>>>(xyz1, xyz2, p_idx, p_w, p_stats);

    // P2W = points2 @ fuse_w[:,128:384]^T   (16384 x 128, K=256)
    mma_gemm<256, false, false, false><<<MSRC / 128, 256, SMEM_K256>>>(
        points2, fuse_w + 128, 384, nullptr, p_p2w,
        nullptr, nullptr, nullptr, nullptr, nullptr, nullptr, nullptr, MSRC / 128);

    // t0 = points1 @ fuse_w[:,0:128]^T + fuse_b + gather(P2W) ; stats0
    mma_gemm<128, false, true, true><<<296, 256, SMEM_K128>>>(
        points1, fuse_w, 384, fuse_b, p_t0,
        nullptr, nullptr, nullptr, p_stats + 0, p_idx, p_w, p_p2w, MPTS / 128);

    // t1 = gelu(bn0(t0)) @ w1^T + b1 ; stats1   (aff computed in-kernel)
    mma_gemm<128, true, false, true><<<296, 256, SMEM_K128>>>(
        p_t0, w1, 128, b1, p_t1,
        p_stats + 0, fuse_g, fuse_bt, p_stats + 256, nullptr, nullptr, nullptr, MPTS / 128);

    // t2 = gelu(bn1(t1)) @ w2^T + b2 ; stats2
    mma_gemm<128, true, false, true><<<296, 256, SMEM_K128>>>(
        p_t1, w2, 128, b2, p_t2,
        p_stats + 256, g1, bt1, p_stats + 512, nullptr, nullptr, nullptr, MPTS / 128);

    // out = gelu(bn2(t2) + gelu(bn0(t0)))  (both affines computed in-kernel)
    final_kernel<<<(MPTS * 128 / 4) / 256, 256>>>(
        p_t0, p_t2, p_stats + 0, fuse_g, fuse_bt, p_stats + 512, g2, bt2, out);
}